// round 5
// baseline (speedup 1.0000x reference)
#include <cuda_runtime.h>
#include <cuda_bf16.h>
#include <math.h>

// ---------------- problem constants ----------------
#define F_IN   256
#define HEADS  8
#define HID    8
#define D1     64          // HEADS*HID
#define CLS    40
#define NEG_SLOPE 0.2f

// ---------------- scratch layout (floats) ----------------
#define NMAX        100000
#define OFF_H1      0ull                 // N*64
#define OFF_AS1     6400000ull           // N*8
#define OFF_AD1     7200000ull           // N*8
#define OFF_H2      8000000ull           // N*40
#define OFF_AS2     12000000ull          // N
#define OFF_AD2     12100000ull          // N
#define OFF_DEN1    12200000ull          // N*8   (zeroed)
#define OFF_AGG1    13000000ull          // N*64  (zeroed)
#define OFF_DEN2    19400000ull          // N     (zeroed)
#define OFF_AGG2    19500000ull          // N*40  (zeroed)
#define TOTAL_SCR   23500000ull
#define ZERO_OFF    12200000ull
#define ZERO_LEN    11300000ull

__device__ __align__(16) float g_scratch[TOTAL_SCR];

// ---------------- helpers ----------------
__device__ __forceinline__ float lrelu(float v) { return v > 0.f ? v : NEG_SLOPE * v; }

__device__ __forceinline__ void red_add_v4(float* addr, float a, float b, float c, float d) {
    asm volatile("red.global.add.v4.f32 [%0], {%1,%2,%3,%4};"
                 :: "l"(addr), "f"(a), "f"(b), "f"(c), "f"(d) : "memory");
}
__device__ __forceinline__ void red_add_f32(float* addr, float v) {
    asm volatile("red.global.add.f32 [%0], %1;" :: "l"(addr), "f"(v) : "memory");
}

// ---------------- zero scratch ----------------
__global__ void zero_kernel() {
    size_t i = (size_t)blockIdx.x * blockDim.x + threadIdx.x;
    float4* p = (float4*)(g_scratch + ZERO_OFF);
    size_t n4 = ZERO_LEN / 4;
    size_t stride = (size_t)gridDim.x * blockDim.x;
    for (; i < n4; i += stride) p[i] = make_float4(0.f, 0.f, 0.f, 0.f);
}

// ---------------- layer 1 GEMM + attention logits ----------------
// h1 = x @ W1 (N x 64); as1[n,h] = sum_c h1[n,h,c]*a_src1[h,c]; ad1 likewise.
// 256 threads = 32 nodes/block; thread -> (node = t/8, head = t%8), 8 channels.
// K tiled in 4 chunks of 64 -> static smem < 48KB.
__global__ void gemm1_kernel(const float* __restrict__ x, const float* __restrict__ W1,
                             const float* __restrict__ a_src, const float* __restrict__ a_dst,
                             int N) {
    __shared__ float Ws[64 * 64];     // [k within chunk][64 out-ch]  16KB
    __shared__ float xs[32 * 68];     // [node][64 k-vals] padded     8.5KB
    int t = threadIdx.x;
    int node0 = blockIdx.x * 32;
    int nn = t >> 3, cg = t & 7;
    int node = node0 + nn;

    float acc[8];
    #pragma unroll
    for (int i = 0; i < 8; i++) acc[i] = 0.f;

    for (int kt = 0; kt < 4; kt++) {
        __syncthreads();
        const float4* Wg4 = (const float4*)(W1 + kt * 64 * 64);
        float4* Ws4 = (float4*)Ws;
        #pragma unroll
        for (int i = 0; i < 4; i++) Ws4[t + i * 256] = Wg4[t + i * 256];
        #pragma unroll
        for (int it = 0; it < 2; it++) {
            int i = t + it * 256;
            int xn = i >> 4, c4 = i & 15;
            int nd = node0 + xn;
            float4 v = make_float4(0.f, 0.f, 0.f, 0.f);
            if (nd < N) v = ((const float4*)x)[(size_t)nd * 64 + kt * 16 + c4];
            *((float4*)(xs + xn * 68 + c4 * 4)) = v;
        }
        __syncthreads();

        const float* xr = xs + nn * 68;
        const float4* Wsv = (const float4*)Ws;
        #pragma unroll 4
        for (int k = 0; k < 64; k++) {
            float xv = xr[k];
            float4 w0 = Wsv[k * 16 + cg * 2];
            float4 w1 = Wsv[k * 16 + cg * 2 + 1];
            acc[0] += xv * w0.x; acc[1] += xv * w0.y; acc[2] += xv * w0.z; acc[3] += xv * w0.w;
            acc[4] += xv * w1.x; acc[5] += xv * w1.y; acc[6] += xv * w1.z; acc[7] += xv * w1.w;
        }
    }

    if (node < N) {
        float* h1 = g_scratch + OFF_H1 + (size_t)node * 64 + cg * 8;
        ((float4*)h1)[0] = make_float4(acc[0], acc[1], acc[2], acc[3]);
        ((float4*)h1)[1] = make_float4(acc[4], acc[5], acc[6], acc[7]);
        float as = 0.f, ad = 0.f;
        #pragma unroll
        for (int i = 0; i < 8; i++) {
            as += acc[i] * __ldg(&a_src[cg * 8 + i]);
            ad += acc[i] * __ldg(&a_dst[cg * 8 + i]);
        }
        g_scratch[OFF_AS1 + (size_t)node * 8 + cg] = as;
        g_scratch[OFF_AD1 + (size_t)node * 8 + cg] = ad;
    }
}

// ---------------- layer 1 edge softmax denominator ----------------
__global__ void edge1_denom_kernel(const int* __restrict__ ei, int E, int Etot, int N) {
    int e = blockIdx.x * blockDim.x + threadIdx.x;
    if (e >= Etot) return;
    int s, d;
    if (e < E) { s = ei[e]; d = ei[E + e]; } else { s = d = e - E; }
    if ((unsigned)s >= (unsigned)N || (unsigned)d >= (unsigned)N) return;  // dtype safety
    const float4* as = (const float4*)(g_scratch + OFF_AS1 + (size_t)s * 8);
    const float4* ad = (const float4*)(g_scratch + OFF_AD1 + (size_t)d * 8);
    float4 a0 = as[0], a1 = as[1], b0 = ad[0], b1 = ad[1];
    float e0 = __expf(lrelu(a0.x + b0.x));
    float e1 = __expf(lrelu(a0.y + b0.y));
    float e2 = __expf(lrelu(a0.z + b0.z));
    float e3 = __expf(lrelu(a0.w + b0.w));
    float e4 = __expf(lrelu(a1.x + b1.x));
    float e5 = __expf(lrelu(a1.y + b1.y));
    float e6 = __expf(lrelu(a1.z + b1.z));
    float e7 = __expf(lrelu(a1.w + b1.w));
    float* den = g_scratch + OFF_DEN1 + (size_t)d * 8;
    red_add_v4(den, e0, e1, e2, e3);
    red_add_v4(den + 4, e4, e5, e6, e7);
}

// ---------------- layer 1 weighted aggregation ----------------
// one thread per (edge, head)
__global__ void edge1_agg_kernel(const int* __restrict__ ei, int E, int Etot, int N) {
    int idx = blockIdx.x * blockDim.x + threadIdx.x;
    if (idx >= Etot * 8) return;
    int e = idx >> 3, h = idx & 7;
    int s, d;
    if (e < E) { s = ei[e]; d = ei[E + e]; } else { s = d = e - E; }
    if ((unsigned)s >= (unsigned)N || (unsigned)d >= (unsigned)N) return;
    float lin = g_scratch[OFF_AS1 + (size_t)s * 8 + h] + g_scratch[OFF_AD1 + (size_t)d * 8 + h];
    float ex = __expf(lrelu(lin));
    float den = g_scratch[OFF_DEN1 + (size_t)d * 8 + h];
    float alpha = __fdividef(ex, den);
    const float4* hv = (const float4*)(g_scratch + OFF_H1 + (size_t)s * 64 + h * 8);
    float4 v0 = hv[0], v1 = hv[1];
    float* dst = g_scratch + OFF_AGG1 + (size_t)d * 64 + h * 8;
    red_add_v4(dst, v0.x * alpha, v0.y * alpha, v0.z * alpha, v0.w * alpha);
    red_add_v4(dst + 4, v1.x * alpha, v1.y * alpha, v1.z * alpha, v1.w * alpha);
}

// ---------------- ELU + layer 2 GEMM + logits ----------------
__global__ void gemm2_kernel(const float* __restrict__ W2, const float* __restrict__ a_src2,
                             const float* __restrict__ a_dst2, const float* __restrict__ b1,
                             int N) {
    __shared__ float Ws[64 * 40];
    __shared__ float xs[32 * 65];
    int t = threadIdx.x;
    int node0 = blockIdx.x * 32;

    for (int i = t; i < 64 * 40; i += 256) Ws[i] = W2[i];
    #pragma unroll
    for (int it = 0; it < 8; it++) {
        int i = t + it * 256;
        int nn = i >> 6, k = i & 63;
        int node = node0 + nn;
        float v = 0.f;
        if (node < N) {
            v = g_scratch[OFF_AGG1 + (size_t)node * 64 + k] + __ldg(&b1[k]);
            v = v > 0.f ? v : expm1f(v);   // ELU
        }
        xs[nn * 65 + k] = v;
    }
    __syncthreads();

    int nn = t >> 3, cg = t & 7;
    int node = node0 + nn;
    float acc[5];
    #pragma unroll
    for (int j = 0; j < 5; j++) acc[j] = 0.f;
    const float* xr = xs + nn * 65;

    #pragma unroll 4
    for (int k = 0; k < 64; k++) {
        float xv = xr[k];
        #pragma unroll
        for (int j = 0; j < 5; j++) acc[j] += xv * Ws[k * 40 + cg * 5 + j];
    }

    float pa = 0.f, pd = 0.f;
    #pragma unroll
    for (int j = 0; j < 5; j++) {
        pa += acc[j] * __ldg(&a_src2[cg * 5 + j]);
        pd += acc[j] * __ldg(&a_dst2[cg * 5 + j]);
    }
    #pragma unroll
    for (int o = 4; o >= 1; o >>= 1) {
        pa += __shfl_down_sync(0xffffffffu, pa, o, 8);
        pd += __shfl_down_sync(0xffffffffu, pd, o, 8);
    }
    if (node < N) {
        float* h2 = g_scratch + OFF_H2 + (size_t)node * 40 + cg * 5;
        #pragma unroll
        for (int j = 0; j < 5; j++) h2[j] = acc[j];
        if (cg == 0) {
            g_scratch[OFF_AS2 + node] = pa;
            g_scratch[OFF_AD2 + node] = pd;
        }
    }
}

// ---------------- layer 2 edge softmax denominator ----------------
__global__ void edge2_denom_kernel(const int* __restrict__ ei, int E, int Etot, int N) {
    int e = blockIdx.x * blockDim.x + threadIdx.x;
    if (e >= Etot) return;
    int s, d;
    if (e < E) { s = ei[e]; d = ei[E + e]; } else { s = d = e - E; }
    if ((unsigned)s >= (unsigned)N || (unsigned)d >= (unsigned)N) return;
    float ex = __expf(lrelu(g_scratch[OFF_AS2 + s] + g_scratch[OFF_AD2 + d]));
    red_add_f32(g_scratch + OFF_DEN2 + d, ex);
}

// ---------------- layer 2 weighted aggregation ----------------
// one thread per (edge, quad of channels): 10 quads x 4 = 40 channels
__global__ void edge2_agg_kernel(const int* __restrict__ ei, int E, int Etot, int N) {
    int idx = blockIdx.x * blockDim.x + threadIdx.x;
    if (idx >= Etot * 10) return;
    int e = idx / 10, q = idx - e * 10;
    int s, d;
    if (e < E) { s = ei[e]; d = ei[E + e]; } else { s = d = e - E; }
    if ((unsigned)s >= (unsigned)N || (unsigned)d >= (unsigned)N) return;
    float ex = __expf(lrelu(g_scratch[OFF_AS2 + s] + g_scratch[OFF_AD2 + d]));
    float alpha = __fdividef(ex, g_scratch[OFF_DEN2 + d]);
    float4 v = *(const float4*)(g_scratch + OFF_H2 + (size_t)s * 40 + q * 4);
    red_add_v4(g_scratch + OFF_AGG2 + (size_t)d * 40 + q * 4,
               v.x * alpha, v.y * alpha, v.z * alpha, v.w * alpha);
}

// ---------------- final bias + log_softmax ----------------
// one warp per node, 40 classes
__global__ void finalize_kernel(const float* __restrict__ b2, float* __restrict__ out, int N) {
    int gtid = blockIdx.x * blockDim.x + threadIdx.x;
    int node = gtid >> 5;
    int lane = gtid & 31;
    if (node >= N) return;
    const float* a = g_scratch + OFF_AGG2 + (size_t)node * 40;
    float v0 = a[lane] + __ldg(&b2[lane]);
    int c2 = lane + 32;
    float v1 = (c2 < CLS) ? (a[c2] + __ldg(&b2[c2])) : -INFINITY;
    float m = fmaxf(v0, v1);
    #pragma unroll
    for (int o = 16; o >= 1; o >>= 1) m = fmaxf(m, __shfl_xor_sync(0xffffffffu, m, o));
    float se = __expf(v0 - m) + ((c2 < CLS) ? __expf(v1 - m) : 0.f);
    #pragma unroll
    for (int o = 16; o >= 1; o >>= 1) se += __shfl_xor_sync(0xffffffffu, se, o);
    float lse = m + logf(se);
    out[(size_t)node * 40 + lane] = v0 - lse;
    if (c2 < CLS) out[(size_t)node * 40 + c2] = v1 - lse;
}

// ---------------- launch ----------------
extern "C" void kernel_launch(void* const* d_in, const int* in_sizes, int n_in,
                              void* d_out, int out_size) {
    const float* x      = (const float*)d_in[0];
    const int*   ei     = (const int*)d_in[1];     // edge_index downcast to int32 by harness
    const float* W1     = (const float*)d_in[2];
    const float* a_src1 = (const float*)d_in[3];
    const float* a_dst1 = (const float*)d_in[4];
    const float* b1     = (const float*)d_in[5];
    const float* W2     = (const float*)d_in[6];
    const float* a_src2 = (const float*)d_in[7];
    const float* a_dst2 = (const float*)d_in[8];
    const float* b2     = (const float*)d_in[9];
    float* out = (float*)d_out;

    int N = in_sizes[0] / F_IN;
    int E = in_sizes[1] / 2;
    int Etot = E + N;

    zero_kernel<<<2048, 256>>>();
    gemm1_kernel<<<(N + 31) / 32, 256>>>(x, W1, a_src1, a_dst1, N);
    edge1_denom_kernel<<<(Etot + 255) / 256, 256>>>(ei, E, Etot, N);
    edge1_agg_kernel<<<(Etot * 8 + 255) / 256, 256>>>(ei, E, Etot, N);
    gemm2_kernel<<<(N + 31) / 32, 256>>>(W2, a_src2, a_dst2, b1, N);
    edge2_denom_kernel<<<(Etot + 255) / 256, 256>>>(ei, E, Etot, N);
    edge2_agg_kernel<<<(Etot * 10 + 255) / 256, 256>>>(ei, E, Etot, N);
    finalize_kernel<<<(N * 32 + 255) / 256, 256>>>(b2, out, N);
}